// round 11
// baseline (speedup 1.0000x reference)
#include <cuda_runtime.h>
#include <cuda_fp16.h>
#include <math.h>

#define FF    128
#define F3    384
#define NRBF  20
#define AMAX  50000
#define EMAX  500000
#define PI_F  3.14159265358979323846f
#define RCUT  5.0f
#define KPI   (PI_F / RCUT)

typedef unsigned long long u64;

// scratch (device globals: allocation-free)
__device__ __half g_sbuf[AMAX * F3];    // node MLP output [A,384] fp16
__device__ __half g_vech[AMAX * F3];    // fp16 copy of vectors [A,3,F]
__device__ int    g_cnt[AMAX];
__device__ int    g_cur[AMAX];
__device__ int    g_ii[EMAX];
__device__ int    g_jj[EMAX];
__device__ float  g_dir[EMAX * 3];

// ---- packed fp32x2 helpers -------------------------------------------------
__device__ __forceinline__ u64 pk2(float lo, float hi) {
    u64 r; asm("mov.b64 %0, {%1, %2};" : "=l"(r) : "f"(lo), "f"(hi)); return r;
}
__device__ __forceinline__ u64 fma2(u64 a, u64 b, u64 c) {
    u64 d; asm("fma.rn.f32x2 %0, %1, %2, %3;" : "=l"(d) : "l"(a), "l"(b), "l"(c));
    return d;
}
__device__ __forceinline__ float2 upk2(u64 v) {
    float2 f; asm("mov.b64 {%0, %1}, %2;" : "=f"(f.x), "=f"(f.y) : "l"(v)); return f;
}
// convert 4 packed halves -> float4
__device__ __forceinline__ float4 cvt4(uint2 u) {
    float2 a = __half22float2(*reinterpret_cast<__half2*>(&u.x));
    float2 b = __half22float2(*reinterpret_cast<__half2*>(&u.y));
    return make_float4(a.x, a.y, b.x, b.y);
}

// ---------------------------------------------------------------------------
__global__ void vconv_kernel(const float* __restrict__ vectors, int n4) {
    int t = blockIdx.x * blockDim.x + threadIdx.x;
    if (t >= n4) return;
    float4 v = reinterpret_cast<const float4*>(vectors)[t];
    __half2 h0 = __floats2half2_rn(v.x, v.y);
    __half2 h1 = __floats2half2_rn(v.z, v.w);
    uint2 u;
    u.x = *reinterpret_cast<unsigned*>(&h0);
    u.y = *reinterpret_cast<unsigned*>(&h1);
    *reinterpret_cast<uint2*>(&g_vech[(size_t)t * 4]) = u;
}

__global__ void hist_kernel(const int* __restrict__ idx_j, int E) {
    int e = blockIdx.x * blockDim.x + threadIdx.x;
    if (e < E) atomicAdd(&g_cnt[idx_j[e]], 1);
}

// single-block exclusive scan over g_cnt -> g_cur (1024 threads)
__global__ __launch_bounds__(1024) void scan_kernel(int A) {
    __shared__ int wsum[32];
    __shared__ int s_carry;
    const int tid = threadIdx.x, lane = tid & 31, w = tid >> 5;
    if (tid == 0) s_carry = 0;
    __syncthreads();
    for (int base = 0; base < A; base += 1024) {
        int v = (base + tid < A) ? g_cnt[base + tid] : 0;
        int incl = v;
#pragma unroll
        for (int d = 1; d < 32; d <<= 1) {
            int t = __shfl_up_sync(0xffffffffu, incl, d);
            if (lane >= d) incl += t;
        }
        if (lane == 31) wsum[w] = incl;
        __syncthreads();
        if (w == 0) {
            int s = wsum[lane];
#pragma unroll
            for (int d = 1; d < 32; d <<= 1) {
                int t = __shfl_up_sync(0xffffffffu, s, d);
                if (lane >= d) s += t;
            }
            wsum[lane] = s;
        }
        __syncthreads();
        int blockIncl = incl + (w > 0 ? wsum[w - 1] : 0);
        int carry = s_carry;
        if (base + tid < A) g_cur[base + tid] = carry + blockIncl - v;
        __syncthreads();
        if (tid == 1023) s_carry = carry + blockIncl;
        __syncthreads();
    }
}

__global__ void scatter_kernel(const int* __restrict__ idx_i,
                               const int* __restrict__ idx_j,
                               const float* __restrict__ directions, int E) {
    int e = blockIdx.x * blockDim.x + threadIdx.x;
    if (e >= E) return;
    int j = idx_j[e];
    int pos = atomicAdd(&g_cur[j], 1);
    g_ii[pos] = idx_i[e];
    g_jj[pos] = j;
    g_dir[(size_t)pos * 3 + 0] = directions[(size_t)e * 3 + 0];
    g_dir[(size_t)pos * 3 + 1] = directions[(size_t)e * 3 + 1];
    g_dir[(size_t)pos * 3 + 2] = directions[(size_t)e * 3 + 2];
}

// ---------------------------------------------------------------------------
// Node MLP: 16 rows per block (8 per thread-half), 256 threads, FFMA2.
// (Verbatim from the 597us champion except fp16 output store.)
__global__ __launch_bounds__(256, 2) void mlp_kernel(
    const float* __restrict__ scalars, const float* __restrict__ W1,
    const float* __restrict__ b1, const float* __restrict__ W2,
    const float* __restrict__ b2, int A)
{
    __shared__ float sx[16][FF];
    __shared__ float sh[16][FF];
    const int row0 = blockIdx.x * 16;
    const int tid  = threadIdx.x;

    for (int idx = tid; idx < 16 * 32; idx += 256) {
        int m = idx >> 5, c = idx & 31;
        float4 v = make_float4(0.f, 0.f, 0.f, 0.f);
        if (row0 + m < A)
            v = reinterpret_cast<const float4*>(scalars)[(size_t)(row0 + m) * 32 + c];
        *reinterpret_cast<float4*>(&sx[m][c * 4]) = v;
    }
    __syncthreads();

    const int n  = tid & 127;
    const int m0 = (tid >> 7) * 8;

    u64 acc[8];
#pragma unroll
    for (int i = 0; i < 8; i++) acc[i] = 0ull;

    for (int k = 0; k < FF; k += 4) {
        u64 wp0 = pk2(W1[(k + 0) * FF + n], W1[(k + 1) * FF + n]);
        u64 wp1 = pk2(W1[(k + 2) * FF + n], W1[(k + 3) * FF + n]);
#pragma unroll
        for (int i = 0; i < 8; i++) {
            ulonglong2 x2 = *reinterpret_cast<const ulonglong2*>(&sx[m0 + i][k]);
            acc[i] = fma2(x2.x, wp0, acc[i]);
            acc[i] = fma2(x2.y, wp1, acc[i]);
        }
    }
    {
        float bb = b1[n];
#pragma unroll
        for (int i = 0; i < 8; i++) {
            float2 p = upk2(acc[i]);
            float x = p.x + p.y + bb;
            sh[m0 + i][n] = x / (1.f + __expf(-x));
        }
    }
    __syncthreads();

    u64 a2[8][3];
#pragma unroll
    for (int i = 0; i < 8; i++)
#pragma unroll
        for (int c = 0; c < 3; c++) a2[i][c] = 0ull;

    for (int k = 0; k < FF; k += 4) {
        u64 wp[3][2];
#pragma unroll
        for (int c = 0; c < 3; c++) {
            wp[c][0] = pk2(W2[(k + 0) * F3 + n + c * 128], W2[(k + 1) * F3 + n + c * 128]);
            wp[c][1] = pk2(W2[(k + 2) * F3 + n + c * 128], W2[(k + 3) * F3 + n + c * 128]);
        }
#pragma unroll
        for (int i = 0; i < 8; i++) {
            ulonglong2 h2 = *reinterpret_cast<const ulonglong2*>(&sh[m0 + i][k]);
#pragma unroll
            for (int c = 0; c < 3; c++) {
                a2[i][c] = fma2(h2.x, wp[c][0], a2[i][c]);
                a2[i][c] = fma2(h2.y, wp[c][1], a2[i][c]);
            }
        }
    }
    {
        float c0 = b2[n], c1 = b2[n + 128], c2v = b2[n + 256];
#pragma unroll
        for (int i = 0; i < 8; i++) {
            int row = row0 + m0 + i;
            if (row < A) {
                float2 p0 = upk2(a2[i][0]);
                float2 p1 = upk2(a2[i][1]);
                float2 p2 = upk2(a2[i][2]);
                g_sbuf[(size_t)row * F3 + n]       = __float2half(p0.x + p0.y + c0);
                g_sbuf[(size_t)row * F3 + n + 128] = __float2half(p1.x + p1.y + c1);
                g_sbuf[(size_t)row * F3 + n + 256] = __float2half(p2.x + p2.y + c2v);
            }
        }
    }
}

// ---------------------------------------------------------------------------
__device__ __forceinline__ void red4(float* p, float4 v) {
    asm volatile("red.global.add.v4.f32 [%0], {%1, %2, %3, %4};"
                 :: "l"(p), "f"(v.x), "f"(v.y), "f"(v.z), "f"(v.w)
                 : "memory");
}

#define EPW 4   // edges per warp

// Edge kernel over j-SORTED edges: within a 4-edge group, consecutive edges
// usually share idx_j (avg run ~10), so per-edge red4s are aggregated in
// registers and flushed only at j-changes/group end (~3x fewer REDs).
// Gathers (random idx_i) hit the L2-resident fp16 g_sbuf/g_vech.
// Aggregation state lives ONLY in the epilogue — nothing added across the
// unrolled rbf loop (the proven no-spill shape).
__global__ __launch_bounds__(256, 2) void edge_kernel(
    const float* __restrict__ Wr, const float* __restrict__ br,
    float* __restrict__ out_v, float* __restrict__ out_s, int E)
{
    __shared__ float4 swr[NRBF * 96];   // Wr [20][384] as float4
    __shared__ float  sbr[F3];

    const int tid = threadIdx.x;
    for (int i2 = tid; i2 < NRBF * 96; i2 += 256)
        swr[i2] = reinterpret_cast<const float4*>(Wr)[i2];
    for (int i2 = tid; i2 < F3; i2 += 256) sbr[i2] = br[i2];
    __syncthreads();

    const int warp = tid >> 5;
    const int lane = tid & 31;
    const int ebase = (blockIdx.x * 8 + warp) * EPW;

    float d0[EPW], d1[EPW], d2[EPW], c2r[EPW], scur[EPW], sprev[EPW];
    int   ii[EPW], jj[EPW];

#pragma unroll
    for (int e = 0; e < EPW; e++) {
        int ee = ebase + e;
        bool v = (ee < E);
        d0[e] = 1.f; d1[e] = 0.f; d2[e] = 0.f; ii[e] = 0; jj[e] = -1;
        if (v) {
            d0[e] = g_dir[(size_t)ee * 3 + 0];
            d1[e] = g_dir[(size_t)ee * 3 + 1];
            d2[e] = g_dir[(size_t)ee * 3 + 2];
            ii[e] = g_ii[ee];
            jj[e] = g_jj[ee];
        }
        float nrm = sqrtf(d0[e] * d0[e] + d1[e] * d1[e] + d2[e] * d2[e]);
        float x = KPI * nrm;
        float s1, c1;
        sincosf(x, &s1, &c1);
        c2r[e]   = 2.f * c1;
        scur[e]  = s1;
        sprev[e] = 0.f;
    }

    ulonglong2 aA[EPW], aB[EPW], aC[EPW];
#pragma unroll
    for (int e = 0; e < EPW; e++) {
        aA[e] = make_ulonglong2(0ull, 0ull);
        aB[e] = make_ulonglong2(0ull, 0ull);
        aC[e] = make_ulonglong2(0ull, 0ull);
    }

#pragma unroll
    for (int k = 0; k < NRBF; k++) {
        ulonglong2 wA = *reinterpret_cast<const ulonglong2*>(&swr[k * 96 + lane]);
        ulonglong2 wB = *reinterpret_cast<const ulonglong2*>(&swr[k * 96 + 32 + lane]);
        ulonglong2 wC = *reinterpret_cast<const ulonglong2*>(&swr[k * 96 + 64 + lane]);
#pragma unroll
        for (int e = 0; e < EPW; e++) {
            float s = scur[e];
            u64 sd = pk2(s, s);
            aA[e].x = fma2(wA.x, sd, aA[e].x);
            aA[e].y = fma2(wA.y, sd, aA[e].y);
            aB[e].x = fma2(wB.x, sd, aB[e].x);
            aB[e].y = fma2(wB.y, sd, aB[e].y);
            aC[e].x = fma2(wC.x, sd, aC[e].x);
            aC[e].y = fma2(wC.y, sd, aC[e].y);
            float t = c2r[e] * s - sprev[e];
            sprev[e] = s;
            scur[e]  = t;
        }
    }

    // ---- epilogue: per-edge combine with j-run aggregation ----
    const int f4 = lane * 4;
    float4 brA = *reinterpret_cast<const float4*>(&sbr[f4]);
    float4 brB = *reinterpret_cast<const float4*>(&sbr[128 + f4]);
    float4 brC = *reinterpret_cast<const float4*>(&sbr[256 + f4]);

    float4 gS  = make_float4(0.f, 0.f, 0.f, 0.f);
    float4 g0  = gS, g1 = gS, g2 = gS;
    int prevj = -1;

#define FLUSH()                                                                \
    do { if (prevj >= 0) {                                                     \
        red4(out_s + (size_t)prevj * FF + f4, gS);                             \
        red4(out_v + (size_t)prevj * F3 + f4, g0);                             \
        red4(out_v + (size_t)prevj * F3 + 128 + f4, g1);                       \
        red4(out_v + (size_t)prevj * F3 + 256 + f4, g2);                       \
    } } while (0)

#pragma unroll
    for (int e = 0; e < EPW; e++) {
        if (ebase + e < E) {
            float dx = d0[e], dy = d1[e], dz = d2[e];
            float nrm = sqrtf(dx * dx + dy * dy + dz * dz);
            float inv = 1.f / nrm;
            float c1  = __cosf(KPI * nrm);
            float delta = nrm - RCUT;
            float mask  = fminf(delta, 0.f) / delta;
            float f  = 0.5f * (c1 + 1.f) * mask;
            float sc = f * inv;

            float2 pAx = upk2(aA[e].x), pAy = upk2(aA[e].y);
            float2 pBx = upk2(aB[e].x), pBy = upk2(aB[e].y);
            float2 pCx = upk2(aC[e].x), pCy = upk2(aC[e].y);

            float4 rA, rB, rC;
            rA.x = sc * pAx.x + f * brA.x; rA.y = sc * pAx.y + f * brA.y;
            rA.z = sc * pAy.x + f * brA.z; rA.w = sc * pAy.y + f * brA.w;
            rB.x = sc * pBx.x + f * brB.x; rB.y = sc * pBx.y + f * brB.y;
            rB.z = sc * pBy.x + f * brB.z; rB.w = sc * pBy.y + f * brB.w;
            rC.x = sc * pCx.x + f * brC.x; rC.y = sc * pCx.y + f * brC.y;
            rC.z = sc * pCy.x + f * brC.z; rC.w = sc * pCy.y + f * brC.w;

            size_t ib = (size_t)ii[e] * F3 + f4;
            float4 sA = cvt4(*reinterpret_cast<const uint2*>(&g_sbuf[ib]));
            float4 sB = cvt4(*reinterpret_cast<const uint2*>(&g_sbuf[ib + 128]));
            float4 sC = cvt4(*reinterpret_cast<const uint2*>(&g_sbuf[ib + 256]));

            float4 ds, dv1, dv2;
            ds.x  = sA.x * rA.x; ds.y  = sA.y * rA.y;
            ds.z  = sA.z * rA.z; ds.w  = sA.w * rA.w;
            dv1.x = sB.x * rB.x; dv1.y = sB.y * rB.y;
            dv1.z = sB.z * rB.z; dv1.w = sB.w * rB.w;
            dv2.x = sC.x * rC.x; dv2.y = sC.y * rC.y;
            dv2.z = sC.z * rC.z; dv2.w = sC.w * rC.w;

            float dh0 = dx * inv, dh1 = dy * inv, dh2 = dz * inv;

            float4 v0 = cvt4(*reinterpret_cast<const uint2*>(&g_vech[ib]));
            float4 v1 = cvt4(*reinterpret_cast<const uint2*>(&g_vech[ib + 128]));
            float4 v2 = cvt4(*reinterpret_cast<const uint2*>(&g_vech[ib + 256]));

            float4 ct0, ct1, ct2;
            ct0.x = v0.x * dv1.x + dv2.x * dh0; ct0.y = v0.y * dv1.y + dv2.y * dh0;
            ct0.z = v0.z * dv1.z + dv2.z * dh0; ct0.w = v0.w * dv1.w + dv2.w * dh0;
            ct1.x = v1.x * dv1.x + dv2.x * dh1; ct1.y = v1.y * dv1.y + dv2.y * dh1;
            ct1.z = v1.z * dv1.z + dv2.z * dh1; ct1.w = v1.w * dv1.w + dv2.w * dh1;
            ct2.x = v2.x * dv1.x + dv2.x * dh2; ct2.y = v2.y * dv1.y + dv2.y * dh2;
            ct2.z = v2.z * dv1.z + dv2.z * dh2; ct2.w = v2.w * dv1.w + dv2.w * dh2;

            if (jj[e] == prevj) {
                gS.x += ds.x;  gS.y += ds.y;  gS.z += ds.z;  gS.w += ds.w;
                g0.x += ct0.x; g0.y += ct0.y; g0.z += ct0.z; g0.w += ct0.w;
                g1.x += ct1.x; g1.y += ct1.y; g1.z += ct1.z; g1.w += ct1.w;
                g2.x += ct2.x; g2.y += ct2.y; g2.z += ct2.z; g2.w += ct2.w;
            } else {
                FLUSH();
                gS = ds; g0 = ct0; g1 = ct1; g2 = ct2;
                prevj = jj[e];
            }
        }
    }
    FLUSH();
#undef FLUSH
}

// ---------------------------------------------------------------------------
extern "C" void kernel_launch(void* const* d_in, const int* in_sizes, int n_in,
                              void* d_out, int out_size) {
    const float* vectors    = (const float*)d_in[0];
    const float* scalars    = (const float*)d_in[1];
    const float* directions = (const float*)d_in[2];
    const int*   idx_i      = (const int*)d_in[3];
    const int*   idx_j      = (const int*)d_in[4];
    const float* W1         = (const float*)d_in[5];
    const float* b1         = (const float*)d_in[6];
    const float* W2         = (const float*)d_in[7];
    const float* b2         = (const float*)d_in[8];
    const float* Wr         = (const float*)d_in[9];
    const float* br         = (const float*)d_in[10];

    const int A = in_sizes[0] / (3 * FF);
    const int E = in_sizes[2] / 3;

    float* out   = (float*)d_out;
    float* out_v = out;                          // delta_v: A x 3 x F
    float* out_s = out + (size_t)A * 3 * FF;     // delta_s: A x 1 x F

    static void* p_cnt = nullptr;
    static cudaStream_t s2 = nullptr;
    static cudaEvent_t ev0 = nullptr, ev1 = nullptr;
    if (!p_cnt) {
        cudaGetSymbolAddress(&p_cnt, g_cnt);
        cudaStreamCreateWithFlags(&s2, cudaStreamNonBlocking);
        cudaEventCreateWithFlags(&ev0, cudaEventDisableTiming);
        cudaEventCreateWithFlags(&ev1, cudaEventDisableTiming);
    }

    // fork: output memset + sort-by-j chain + vconv on s2; MLP on main stream
    cudaEventRecord(ev0, 0);
    cudaStreamWaitEvent(s2, ev0, 0);

    cudaMemsetAsync(out, 0, (size_t)out_size * sizeof(float), s2);
    cudaMemsetAsync(p_cnt, 0, (size_t)A * sizeof(int), s2);
    hist_kernel<<<(E + 255) / 256, 256, 0, s2>>>(idx_j, E);
    scan_kernel<<<1, 1024, 0, s2>>>(A);
    scatter_kernel<<<(E + 255) / 256, 256, 0, s2>>>(idx_i, idx_j, directions, E);
    {
        int n4 = (A * F3) / 4;
        vconv_kernel<<<(n4 + 255) / 256, 256, 0, s2>>>(vectors, n4);
    }
    cudaEventRecord(ev1, s2);

    mlp_kernel<<<(A + 15) / 16, 256>>>(scalars, W1, b1, W2, b2, A);

    // join, then edge-parallel combine with aggregated vector reductions
    cudaStreamWaitEvent(0, ev1, 0);
    edge_kernel<<<(E + (8 * EPW) - 1) / (8 * EPW), 256>>>(
        Wr, br, out_v, out_s, E);
}